// round 1
// baseline (speedup 1.0000x reference)
#include <cuda_runtime.h>
#include <cuda_bf16.h>
#include <math.h>

// Problem constants
#define BB   8
#define TT   1024
#define DIN  256
#define CH   1024   // D_H1
#define OO   1024   // D_H2
#define KW   9

// Scratch (device globals — no allocation allowed)
__device__ float g_h [BB * CH * TT];   // mish(w1(x)), layout [b][c][t]
__device__ float g_y [BB * CH * TT];   // conv output * p_g, [b][c][t]
__device__ float g_y2[BB * TT * OO];   // pointwise output, [b][t][o]
__device__ float g_pwn[BB * OO];       // 1/||p_w[b,:,o]||
__device__ float g_dwn[BB * KW];       // 1/||d_w[b,:,k]||

__device__ __forceinline__ float mishf(float v) {
    float sp = (v > 20.f) ? v : log1pf(__expf(v));
    return v * tanhf(sp);
}

// ---------------------------------------------------------------------------
// Norm kernels
// ---------------------------------------------------------------------------
__global__ void dwn_kernel(const float* __restrict__ d_w) {
    int b = blockIdx.x / KW, k = blockIdx.x % KW;
    __shared__ float red[256];
    float s = 0.f;
    for (int c = threadIdx.x; c < CH; c += 256) {
        float v = d_w[((long)b * CH + c) * KW + k];
        s += v * v;
    }
    red[threadIdx.x] = s;
    __syncthreads();
    for (int off = 128; off > 0; off >>= 1) {
        if (threadIdx.x < off) red[threadIdx.x] += red[threadIdx.x + off];
        __syncthreads();
    }
    if (threadIdx.x == 0)
        g_dwn[b * KW + k] = 1.f / fmaxf(sqrtf(red[0]), 1e-12f);
}

// 32 o's per block, 8 c-groups; coalesced 32-wide reads of p_w[b][c][o]
__global__ void pwn_kernel(const float* __restrict__ p_w) {
    int b  = blockIdx.x / (OO / 32);
    int o0 = (blockIdx.x % (OO / 32)) * 32;
    int oi = threadIdx.x & 31, cg = threadIdx.x >> 5;
    int o = o0 + oi;
    float s = 0.f;
    for (int c = cg; c < CH; c += 8) {
        float v = p_w[((long)b * CH + c) * OO + o];
        s += v * v;
    }
    __shared__ float red[8][33];
    red[cg][oi] = s;
    __syncthreads();
    if (cg == 0) {
        float t = 0.f;
        #pragma unroll
        for (int j = 0; j < 8; j++) t += red[j][oi];
        g_pwn[b * OO + o] = 1.f / fmaxf(sqrtf(t), 1e-12f);
    }
}

// ---------------------------------------------------------------------------
// Depthwise conv (K=9, pad 4), channel-normed weights, folds p_g into output
// ---------------------------------------------------------------------------
__global__ void conv_kernel(const float* __restrict__ d_w,
                            const float* __restrict__ d_g,
                            const float* __restrict__ d_b,
                            const float* __restrict__ p_g) {
    int b = blockIdx.x / CH, c = blockIdx.x % CH;
    __shared__ float hrow[TT + 8];
    const float* hp = g_h + ((long)b * CH + c) * TT;
    for (int t = threadIdx.x; t < TT; t += 256) hrow[t + 4] = hp[t];
    if (threadIdx.x < 8)
        hrow[threadIdx.x < 4 ? threadIdx.x : TT + threadIdx.x] = 0.f;
    __syncthreads();

    float gg   = d_g[b * CH + c];
    float pg   = p_g[b * CH + c];
    float bias = d_b[b * CH + c];
    float w[KW];
    #pragma unroll
    for (int k = 0; k < KW; k++)
        w[k] = d_w[((long)b * CH + c) * KW + k] * g_dwn[b * KW + k] * gg;

    float* yp = g_y + ((long)b * CH + c) * TT;
    for (int t = threadIdx.x; t < TT; t += 256) {
        float acc = bias;
        #pragma unroll
        for (int k = 0; k < KW; k++) acc = fmaf(hrow[t + k], w[k], acc);
        yp[t] = acc * pg;
    }
}

// ---------------------------------------------------------------------------
// Tiled SGEMM: C[m][n] = sum_k a(m,k) * b(n,k)
//   TN = true : A is [K][M] (m contiguous), B is [K][N] (n contiguous)
//   TN = false: A is [M][K] (k contiguous), B is [N][K] (k contiguous)
// BM=BN=128, BK=8, 256 threads, 8x8 per-thread tile. All dims multiples of
// tile sizes (M,N in {256,1024}, K in {256,1024}) -> no predication.
// EPI 1: v += e1[m]; mish          (GEMM1, e1 = w1_b)
// EPI 2: v = v*e1[b*OO+n] + e2[b*OO+n]   (GEMM2, e1 = pwn, e2 = p_b)
// EPI 3: v += e1[n] + e2[b*M*N + m*N + n] (GEMM3, e1 = w2_b, e2 = x residual)
// ---------------------------------------------------------------------------
#define BM 128
#define BN 128
#define BK 8
#define PAD 4

template<bool TN, int EPI>
__global__ void __launch_bounds__(256)
gemm_k(const float* __restrict__ A, int ldA, long sA,
       const float* __restrict__ Bm, int ldB, long sB,
       float* __restrict__ Cm, long sC,
       int M, int N, int Kd,
       const float* __restrict__ e1, const float* __restrict__ e2)
{
    __shared__ float As[BK][BM + PAD];
    __shared__ float Bs[BK][BN + PAD];

    int b = blockIdx.z;
    A  += (long)b * sA;
    Bm += (long)b * sB;
    Cm += (long)b * sC;

    int m0 = blockIdx.y * BM, n0 = blockIdx.x * BN;
    int tid = threadIdx.x;
    int tx = tid & 15, ty = tid >> 4;

    float acc[8][8];
    #pragma unroll
    for (int i = 0; i < 8; i++)
        #pragma unroll
        for (int j = 0; j < 8; j++) acc[i][j] = 0.f;

    for (int k0 = 0; k0 < Kd; k0 += BK) {
        float4 av, bv;
        if (TN) {
            int kk = tid >> 5, mm = (tid & 31) * 4;
            av = *(const float4*)&A [(long)(k0 + kk) * ldA + m0 + mm];
            bv = *(const float4*)&Bm[(long)(k0 + kk) * ldB + n0 + mm];
            __syncthreads();
            *(float4*)&As[kk][mm] = av;
            *(float4*)&Bs[kk][mm] = bv;
        } else {
            int row = tid >> 1, kq = (tid & 1) * 4;
            av = *(const float4*)&A [(long)(m0 + row) * ldA + k0 + kq];
            bv = *(const float4*)&Bm[(long)(n0 + row) * ldB + k0 + kq];
            __syncthreads();
            As[kq + 0][row] = av.x; As[kq + 1][row] = av.y;
            As[kq + 2][row] = av.z; As[kq + 3][row] = av.w;
            Bs[kq + 0][row] = bv.x; Bs[kq + 1][row] = bv.y;
            Bs[kq + 2][row] = bv.z; Bs[kq + 3][row] = bv.w;
        }
        __syncthreads();

        #pragma unroll
        for (int kk = 0; kk < BK; kk++) {
            float a[8], bb[8];
            *(float4*)&a[0]  = *(const float4*)&As[kk][ty * 8];
            *(float4*)&a[4]  = *(const float4*)&As[kk][ty * 8 + 4];
            *(float4*)&bb[0] = *(const float4*)&Bs[kk][tx * 8];
            *(float4*)&bb[4] = *(const float4*)&Bs[kk][tx * 8 + 4];
            #pragma unroll
            for (int i = 0; i < 8; i++)
                #pragma unroll
                for (int j = 0; j < 8; j++)
                    acc[i][j] = fmaf(a[i], bb[j], acc[i][j]);
        }
    }

    #pragma unroll
    for (int i = 0; i < 8; i++) {
        int m = m0 + ty * 8 + i;
        #pragma unroll
        for (int j = 0; j < 8; j++) {
            int n = n0 + tx * 8 + j;
            float v = acc[i][j];
            if (EPI == 1) {
                v += e1[m];
                v = mishf(v);
            } else if (EPI == 2) {
                v = v * e1[b * OO + n] + e2[b * OO + n];
            } else if (EPI == 3) {
                v += e1[n] + e2[(long)b * M * N + (long)m * N + n];
            }
            Cm[(long)m * N + n] = v;
        }
    }
}

// ---------------------------------------------------------------------------
extern "C" void kernel_launch(void* const* d_in, const int* in_sizes, int n_in,
                              void* d_out, int out_size) {
    const float* x    = (const float*)d_in[0];
    const float* d_w  = (const float*)d_in[1];
    const float* d_g  = (const float*)d_in[2];
    const float* d_b  = (const float*)d_in[3];
    const float* p_w  = (const float*)d_in[4];
    const float* p_g  = (const float*)d_in[5];
    const float* p_b  = (const float*)d_in[6];
    const float* w1_w = (const float*)d_in[7];
    const float* w1_b = (const float*)d_in[8];
    const float* w2_w = (const float*)d_in[9];
    const float* w2_b = (const float*)d_in[10];
    float* out = (float*)d_out;

    // Device-global scratch addresses (host side needs raw pointers to pass)
    void *p_gh, *p_gy, *p_gy2, *p_gpwn;
    cudaGetSymbolAddress(&p_gh,   g_h);
    cudaGetSymbolAddress(&p_gy,   g_y);
    cudaGetSymbolAddress(&p_gy2,  g_y2);
    cudaGetSymbolAddress(&p_gpwn, g_pwn);
    float* gh   = (float*)p_gh;
    float* gy   = (float*)p_gy;
    float* gy2  = (float*)p_gy2;
    float* gpwn = (float*)p_gpwn;

    // 1) inverse norms for weight-normalization
    dwn_kernel<<<BB * KW, 256>>>(d_w);
    pwn_kernel<<<BB * (OO / 32), 256>>>(p_w);

    // 2) GEMM1 (NT): h[b][c][t] = mish( sum_i w1[c][i]*x[b][t][i] + w1_b[c] )
    {
        dim3 grid(TT / BN, CH / BM, BB);
        gemm_k<false, 1><<<grid, 256>>>(
            w1_w, DIN, 0L,
            x,    DIN, (long)TT * DIN,
            gh,   (long)CH * TT,
            CH, TT, DIN,
            w1_b, nullptr);
    }

    // 3) depthwise conv, folds d_g/d_b/dwn and p_g
    conv_kernel<<<BB * CH, 256>>>(d_w, d_g, d_b, p_g);

    // 4) GEMM2 (TN): y2[b][t][o] = (sum_c y'[b][c][t]*p_w[b][c][o])*pwn[b][o] + p_b[b][o]
    {
        dim3 grid(OO / BN, TT / BM, BB);
        gemm_k<true, 2><<<grid, 256>>>(
            gy,  TT, (long)CH * TT,
            p_w, OO, (long)CH * OO,
            gy2, (long)TT * OO,
            TT, OO, CH,
            gpwn, p_b);
    }

    // 5) GEMM3 (NT): out[b][t][i] = sum_o y2[b][t][o]*w2[i][o] + w2_b[i] + x[b][t][i]
    {
        dim3 grid(DIN / BN, TT / BM, BB);
        gemm_k<false, 3><<<grid, 256>>>(
            gy2,  OO, (long)TT * OO,
            w2_w, OO, 0L,
            out,  (long)TT * DIN,
            TT, DIN, OO,
            w2_b, x);
    }
}

// round 3
// speedup vs baseline: 1.9480x; 1.9480x over previous
#include <cuda_runtime.h>
#include <cuda_bf16.h>
#include <math.h>
#include <stdint.h>

// Problem constants
#define BB   8
#define TT   1024
#define DIN  256
#define CH   1024   // D_H1
#define OO   1024   // D_H2
#define KW   9

typedef __nv_bfloat16 bf16;

// Scratch (device globals — no allocation allowed)
__device__ float g_h [BB * CH * TT];     // mish(w1(x)), [b][c][t]
__device__ float g_y [BB * CH * TT];     // conv out * p_g, [b][c][t]
__device__ float g_pwn[BB * OO];         // 1/||p_w[b,:,o]||
__device__ float g_dwn[BB * KW];         // 1/||d_w[b,:,k]||
// bf16 hi/lo operands
__device__ bf16 g_yTh[BB * TT * CH];     // [b][t][c]
__device__ bf16 g_yTl[BB * TT * CH];
__device__ bf16 g_pTh[BB * OO * CH];     // [b][o][c]
__device__ bf16 g_pTl[BB * OO * CH];
__device__ bf16 g_y2h[BB * TT * OO];     // [b][t][o]
__device__ bf16 g_y2l[BB * TT * OO];
__device__ bf16 g_xh [BB * TT * DIN];    // [b][t][i]
__device__ bf16 g_xl [BB * TT * DIN];
__device__ bf16 g_w1h[CH * DIN];
__device__ bf16 g_w1l[CH * DIN];
__device__ bf16 g_w2h[DIN * OO];
__device__ bf16 g_w2l[DIN * OO];

__device__ __forceinline__ float mishf(float v) {
    float sp = (v > 20.f) ? v : log1pf(__expf(v));
    return v * tanhf(sp);
}

// ---------------------------------------------------------------------------
// Norm kernels
// ---------------------------------------------------------------------------
__global__ void dwn_kernel(const float* __restrict__ d_w) {
    int b = blockIdx.x / KW, k = blockIdx.x % KW;
    __shared__ float red[256];
    float s = 0.f;
    for (int c = threadIdx.x; c < CH; c += 256) {
        float v = d_w[((long)b * CH + c) * KW + k];
        s += v * v;
    }
    red[threadIdx.x] = s;
    __syncthreads();
    for (int off = 128; off > 0; off >>= 1) {
        if (threadIdx.x < off) red[threadIdx.x] += red[threadIdx.x + off];
        __syncthreads();
    }
    if (threadIdx.x == 0)
        g_dwn[b * KW + k] = 1.f / fmaxf(sqrtf(red[0]), 1e-12f);
}

__global__ void pwn_kernel(const float* __restrict__ p_w) {
    int b  = blockIdx.x / (OO / 32);
    int o0 = (blockIdx.x % (OO / 32)) * 32;
    int oi = threadIdx.x & 31, cg = threadIdx.x >> 5;
    int o = o0 + oi;
    float s = 0.f;
    for (int c = cg; c < CH; c += 8) {
        float v = p_w[((long)b * CH + c) * OO + o];
        s += v * v;
    }
    __shared__ float red[8][33];
    red[cg][oi] = s;
    __syncthreads();
    if (cg == 0) {
        float t = 0.f;
        #pragma unroll
        for (int j = 0; j < 8; j++) t += red[j][oi];
        g_pwn[b * OO + o] = 1.f / fmaxf(sqrtf(t), 1e-12f);
    }
}

// ---------------------------------------------------------------------------
// Depthwise conv (K=9, pad 4)
// ---------------------------------------------------------------------------
__global__ void conv_kernel(const float* __restrict__ d_w,
                            const float* __restrict__ d_g,
                            const float* __restrict__ d_b,
                            const float* __restrict__ p_g) {
    int b = blockIdx.x / CH, c = blockIdx.x % CH;
    __shared__ float hrow[TT + 8];
    const float* hp = g_h + ((long)b * CH + c) * TT;
    for (int t = threadIdx.x; t < TT; t += 256) hrow[t + 4] = hp[t];
    if (threadIdx.x < 8)
        hrow[threadIdx.x < 4 ? threadIdx.x : TT + threadIdx.x] = 0.f;
    __syncthreads();

    float gg   = d_g[b * CH + c];
    float pg   = p_g[b * CH + c];
    float bias = d_b[b * CH + c];
    float w[KW];
    #pragma unroll
    for (int k = 0; k < KW; k++)
        w[k] = d_w[((long)b * CH + c) * KW + k] * g_dwn[b * KW + k] * gg;

    float* yp = g_y + ((long)b * CH + c) * TT;
    for (int t = threadIdx.x; t < TT; t += 256) {
        float acc = bias;
        #pragma unroll
        for (int k = 0; k < KW; k++) acc = fmaf(hrow[t + k], w[k], acc);
        yp[t] = acc * pg;
    }
}

// ---------------------------------------------------------------------------
// Elementwise bf16 hi/lo split (no transpose), float4-vectorized
// ---------------------------------------------------------------------------
__global__ void split_kernel(const float* __restrict__ src,
                             bf16* __restrict__ hi, bf16* __restrict__ lo,
                             int n4) {
    int i = blockIdx.x * blockDim.x + threadIdx.x;
    if (i >= n4) return;
    float4 v = ((const float4*)src)[i];
    bf16 h0 = __float2bfloat16(v.x), h1 = __float2bfloat16(v.y);
    bf16 h2 = __float2bfloat16(v.z), h3 = __float2bfloat16(v.w);
    __nv_bfloat162 hA; hA.x = h0; hA.y = h1;
    __nv_bfloat162 hB; hB.x = h2; hB.y = h3;
    __nv_bfloat162 lA, lB;
    lA.x = __float2bfloat16(v.x - __bfloat162float(h0));
    lA.y = __float2bfloat16(v.y - __bfloat162float(h1));
    lB.x = __float2bfloat16(v.z - __bfloat162float(h2));
    lB.y = __float2bfloat16(v.w - __bfloat162float(h3));
    ((__nv_bfloat162*)hi)[i * 2 + 0] = hA;
    ((__nv_bfloat162*)hi)[i * 2 + 1] = hB;
    ((__nv_bfloat162*)lo)[i * 2 + 0] = lA;
    ((__nv_bfloat162*)lo)[i * 2 + 1] = lB;
}

// ---------------------------------------------------------------------------
// Transpose + bf16 hi/lo split: src[b][R][C] fp32 -> hi/lo[b][C][R] bf16
// R = C = 1024. Block (32,8), grid (32, 32, B).
// ---------------------------------------------------------------------------
__global__ void tcvt_kernel(const float* __restrict__ src,
                            bf16* __restrict__ hi, bf16* __restrict__ lo) {
    __shared__ float tile[32][33];
    int b  = blockIdx.z;
    int c0 = blockIdx.x * 32;
    int r0 = blockIdx.y * 32;
    int tx = threadIdx.x, ty = threadIdx.y;
    const float* s = src + ((size_t)b * 1024 + r0) * 1024 + c0;
    #pragma unroll
    for (int i = 0; i < 32; i += 8)
        tile[ty + i][tx] = s[(size_t)(ty + i) * 1024 + tx];
    __syncthreads();
    size_t ob = ((size_t)b * 1024 + c0) * 1024 + r0;
    #pragma unroll
    for (int i = 0; i < 32; i += 8) {
        float v = tile[tx][ty + i];
        bf16 h = __float2bfloat16(v);
        bf16 l = __float2bfloat16(v - __bfloat162float(h));
        hi[ob + (size_t)(ty + i) * 1024 + tx] = h;
        lo[ob + (size_t)(ty + i) * 1024 + tx] = l;
    }
}

// ---------------------------------------------------------------------------
// Warp-MMA helpers (baseline ISA: sm_80+, works on .target sm_100)
// ---------------------------------------------------------------------------
__device__ __forceinline__ uint32_t smem_u32(const void* p) {
    uint32_t a;
    asm("{ .reg .u64 t; cvta.to.shared.u64 t, %1; cvt.u32.u64 %0, t; }"
        : "=r"(a) : "l"(p));
    return a;
}

__device__ __forceinline__ void cpa16(uint32_t s, const void* g) {
    asm volatile("cp.async.cg.shared.global [%0], [%1], 16;"
                 :: "r"(s), "l"(g) : "memory");
}

__device__ __forceinline__ void ldsm4(uint32_t* r, uint32_t a) {
    asm volatile("ldmatrix.sync.aligned.m8n8.x4.shared.b16 {%0,%1,%2,%3}, [%4];"
                 : "=r"(r[0]), "=r"(r[1]), "=r"(r[2]), "=r"(r[3]) : "r"(a));
}

__device__ __forceinline__ void ldsm2(uint32_t* r, uint32_t a) {
    asm volatile("ldmatrix.sync.aligned.m8n8.x2.shared.b16 {%0,%1}, [%2];"
                 : "=r"(r[0]), "=r"(r[1]) : "r"(a));
}

__device__ __forceinline__ void mma16816(float* d, const uint32_t* a,
                                         const uint32_t* b) {
    asm volatile(
        "mma.sync.aligned.m16n8k16.row.col.f32.bf16.bf16.f32 "
        "{%0,%1,%2,%3}, {%4,%5,%6,%7}, {%8,%9}, {%0,%1,%2,%3};"
        : "+f"(d[0]), "+f"(d[1]), "+f"(d[2]), "+f"(d[3])
        : "r"(a[0]), "r"(a[1]), "r"(a[2]), "r"(a[3]), "r"(b[0]), "r"(b[1]));
}

// ---------------------------------------------------------------------------
// bf16 hi/lo split GEMM: C[m][n] = sum_k A(m,k)*B(n,k), 3-pass
// A: [M][K] k-major (hi/lo), B: [N][K] k-major (hi/lo).
// CTA 128x128, BK=32, 8 warps (2x4), warp tile 64x32, cp.async double buffer.
// EPI 1: fp32 out = mish(v + e1[m])            (GEMM1)
// EPI 2: bf16 hi/lo out = v*e1[b*OO+n]+e2[..]  (GEMM2, split output)
// EPI 3: fp32 out = v + e1[n] + e2[b][m][n]    (GEMM3, residual)
// ---------------------------------------------------------------------------
#define MBM 128
#define MBN 128
#define MBK 32
#define ASTR 40                       // bf16 per smem row (80 B, conflict-free)
#define SEG  (128 * ASTR * 2)         // 10240 B per operand segment
#define STG  (4 * SEG)                // Ah,Al,Bh,Bl per stage
#define SMEM_MMA (2 * STG)            // 81920 B

template<int EPI>
__global__ void __launch_bounds__(256, 1)
mma_gemm(const bf16* __restrict__ Ah, const bf16* __restrict__ Al, long sA,
         const bf16* __restrict__ Bh, const bf16* __restrict__ Bl, long sB,
         void* __restrict__ C0, void* __restrict__ C1, long sC,
         int M, int N, int K,
         const float* __restrict__ e1, const float* __restrict__ e2)
{
    extern __shared__ __align__(128) char sm[];
    const uint32_t smb = smem_u32(sm);
    const int tid = threadIdx.x, lane = tid & 31, wid = tid >> 5;
    const int b = blockIdx.z;
    const int m0 = blockIdx.y * MBM, n0 = blockIdx.x * MBN;
    const int wm = wid >> 2, wn = wid & 3;

    const bf16* gAh = Ah + (size_t)b * sA + (size_t)m0 * K;
    const bf16* gAl = Al + (size_t)b * sA + (size_t)m0 * K;
    const bf16* gBh = Bh + (size_t)b * sB + (size_t)n0 * K;
    const bf16* gBl = Bl + (size_t)b * sB + (size_t)n0 * K;

    float acc[4][4][4];
    #pragma unroll
    for (int i = 0; i < 4; i++)
        #pragma unroll
        for (int j = 0; j < 4; j++)
            #pragma unroll
            for (int r = 0; r < 4; r++) acc[i][j][r] = 0.f;

    // --- stage loader: 16B chunks via cp.async ---
    auto issue = [&](int kc, int s) {
        const uint32_t sb = smb + s * STG;
        #pragma unroll
        for (int t = 0; t < 2; t++) {
            int idx = tid + t * 256;          // 0..511
            int row = idx >> 2, c = idx & 3;
            uint32_t so = (uint32_t)(row * (ASTR * 2) + c * 16);
            size_t go = (size_t)row * K + (size_t)kc * MBK + c * 8;
            cpa16(sb + 0 * SEG + so, gAh + go);
            cpa16(sb + 1 * SEG + so, gAl + go);
            cpa16(sb + 2 * SEG + so, gBh + go);
            cpa16(sb + 3 * SEG + so, gBl + go);
        }
        asm volatile("cp.async.commit_group;" ::: "memory");
    };

    auto compute = [&](int s) {
        const uint32_t sb = smb + s * STG;
        #pragma unroll
        for (int ks = 0; ks < 2; ks++) {
            uint32_t ah[4][4], al[4][4], bh[4][2], bl[4][2];
            #pragma unroll
            for (int i = 0; i < 4; i++) {
                uint32_t ad = sb +
                    (uint32_t)((wm * 64 + i * 16 + (lane & 15)) * (ASTR * 2)) +
                    ks * 32 + (lane >> 4) * 16;
                ldsm4(ah[i], ad);
                ldsm4(al[i], ad + SEG);
            }
            #pragma unroll
            for (int j = 0; j < 4; j++) {
                uint32_t bd = sb + 2 * SEG +
                    (uint32_t)((wn * 32 + j * 8 + (lane & 7)) * (ASTR * 2)) +
                    ks * 32 + ((lane >> 3) & 1) * 16;
                ldsm2(bh[j], bd);
                ldsm2(bl[j], bd + SEG);
            }
            #pragma unroll
            for (int i = 0; i < 4; i++)
                #pragma unroll
                for (int j = 0; j < 4; j++) {
                    mma16816(acc[i][j], ah[i], bh[j]);
                    mma16816(acc[i][j], ah[i], bl[j]);
                    mma16816(acc[i][j], al[i], bh[j]);
                }
        }
    };

    const int NK = K / MBK;
    issue(0, 0);
    for (int kc = 0; kc < NK; kc++) {
        asm volatile("cp.async.wait_group 0;" ::: "memory");
        __syncthreads();
        if (kc + 1 < NK) issue(kc + 1, (kc + 1) & 1);
        compute(kc & 1);
        __syncthreads();
    }

    // --- epilogue ---
    const float* E1 = e1;
    const float* E2 = e2;
    if (EPI == 2) { E1 = e1 + b * OO; E2 = e2 + b * OO; }
    if (EPI == 3) { E2 = e2 + (size_t)b * M * N; }

    const int mrow0 = m0 + wm * 64;
    const int ncol0 = n0 + wn * 32;
    #pragma unroll
    for (int i = 0; i < 4; i++) {
        #pragma unroll
        for (int r = 0; r < 2; r++) {
            int m = mrow0 + i * 16 + (lane >> 2) + r * 8;
            #pragma unroll
            for (int j = 0; j < 4; j++) {
                int n = ncol0 + j * 8 + (lane & 3) * 2;
                float v0 = acc[i][j][r * 2 + 0];
                float v1 = acc[i][j][r * 2 + 1];
                size_t off = (size_t)m * N + n;
                if (EPI == 1) {
                    float bb = E1[m];
                    float2 o; o.x = mishf(v0 + bb); o.y = mishf(v1 + bb);
                    *(float2*)((float*)C0 + (size_t)b * sC + off) = o;
                } else if (EPI == 2) {
                    v0 = v0 * E1[n] + E2[n];
                    v1 = v1 * E1[n + 1] + E2[n + 1];
                    __nv_bfloat162 hv, lv;
                    hv.x = __float2bfloat16(v0);
                    hv.y = __float2bfloat16(v1);
                    lv.x = __float2bfloat16(v0 - __bfloat162float(hv.x));
                    lv.y = __float2bfloat16(v1 - __bfloat162float(hv.y));
                    *(__nv_bfloat162*)((bf16*)C0 + (size_t)b * sC + off) = hv;
                    *(__nv_bfloat162*)((bf16*)C1 + (size_t)b * sC + off) = lv;
                } else {
                    float2 o;
                    o.x = v0 + E1[n]     + E2[off];
                    o.y = v1 + E1[n + 1] + E2[off + 1];
                    *(float2*)((float*)C0 + (size_t)b * sC + off) = o;
                }
            }
        }
    }
}

// ---------------------------------------------------------------------------
extern "C" void kernel_launch(void* const* d_in, const int* in_sizes, int n_in,
                              void* d_out, int out_size) {
    const float* x    = (const float*)d_in[0];
    const float* d_w  = (const float*)d_in[1];
    const float* d_g  = (const float*)d_in[2];
    const float* d_b  = (const float*)d_in[3];
    const float* p_w  = (const float*)d_in[4];
    const float* p_g  = (const float*)d_in[5];
    const float* p_b  = (const float*)d_in[6];
    const float* w1_w = (const float*)d_in[7];
    const float* w1_b = (const float*)d_in[8];
    const float* w2_w = (const float*)d_in[9];
    const float* w2_b = (const float*)d_in[10];
    float* out = (float*)d_out;

    void *p_gh, *p_gy, *p_gpwn;
    void *p_yth, *p_ytl, *p_pth, *p_ptl, *p_y2h, *p_y2l;
    void *p_xh, *p_xl, *p_w1h, *p_w1l, *p_w2h, *p_w2l;
    cudaGetSymbolAddress(&p_gh,   g_h);
    cudaGetSymbolAddress(&p_gy,   g_y);
    cudaGetSymbolAddress(&p_gpwn, g_pwn);
    cudaGetSymbolAddress(&p_yth,  g_yTh);
    cudaGetSymbolAddress(&p_ytl,  g_yTl);
    cudaGetSymbolAddress(&p_pth,  g_pTh);
    cudaGetSymbolAddress(&p_ptl,  g_pTl);
    cudaGetSymbolAddress(&p_y2h,  g_y2h);
    cudaGetSymbolAddress(&p_y2l,  g_y2l);
    cudaGetSymbolAddress(&p_xh,   g_xh);
    cudaGetSymbolAddress(&p_xl,   g_xl);
    cudaGetSymbolAddress(&p_w1h,  g_w1h);
    cudaGetSymbolAddress(&p_w1l,  g_w1l);
    cudaGetSymbolAddress(&p_w2h,  g_w2h);
    cudaGetSymbolAddress(&p_w2l,  g_w2l);
    float* gh   = (float*)p_gh;
    float* gy   = (float*)p_gy;
    float* gpwn = (float*)p_gpwn;

    cudaFuncSetAttribute(mma_gemm<1>,
                         cudaFuncAttributeMaxDynamicSharedMemorySize, SMEM_MMA);
    cudaFuncSetAttribute(mma_gemm<2>,
                         cudaFuncAttributeMaxDynamicSharedMemorySize, SMEM_MMA);
    cudaFuncSetAttribute(mma_gemm<3>,
                         cudaFuncAttributeMaxDynamicSharedMemorySize, SMEM_MMA);

    // 1) norms + input conversions (independent)
    dwn_kernel<<<BB * KW, 256>>>(d_w);
    pwn_kernel<<<BB * (OO / 32), 256>>>(p_w);
    split_kernel<<<(BB * TT * DIN / 4 + 255) / 256, 256>>>(
        x, (bf16*)p_xh, (bf16*)p_xl, BB * TT * DIN / 4);
    split_kernel<<<(CH * DIN / 4 + 255) / 256, 256>>>(
        w1_w, (bf16*)p_w1h, (bf16*)p_w1l, CH * DIN / 4);
    split_kernel<<<(DIN * OO / 4 + 255) / 256, 256>>>(
        w2_w, (bf16*)p_w2h, (bf16*)p_w2l, DIN * OO / 4);
    {
        dim3 grid(32, 32, BB);
        tcvt_kernel<<<grid, dim3(32, 8)>>>(p_w, (bf16*)p_pth, (bf16*)p_ptl);
    }

    // 2) GEMM1: h[b][c][t] = mish(w1 . x + w1_b)   M=CH, N=TT, K=DIN
    {
        dim3 grid(TT / MBN, CH / MBM, BB);
        mma_gemm<1><<<grid, 256, SMEM_MMA>>>(
            (const bf16*)p_w1h, (const bf16*)p_w1l, 0L,
            (const bf16*)p_xh,  (const bf16*)p_xl,  (long)TT * DIN,
            gh, nullptr, (long)CH * TT,
            CH, TT, DIN, w1_b, nullptr);
    }

    // 3) depthwise conv
    conv_kernel<<<BB * CH, 256>>>(d_w, d_g, d_b, p_g);

    // 3b) transpose+split y -> yT
    {
        dim3 grid(32, 32, BB);
        tcvt_kernel<<<grid, dim3(32, 8)>>>(gy, (bf16*)p_yth, (bf16*)p_ytl);
    }

    // 4) GEMM2: y2[b][t][o] = (yT . pT)*pwn + p_b   M=TT, N=OO, K=CH
    //    output split directly to bf16 hi/lo
    {
        dim3 grid(OO / MBN, TT / MBM, BB);
        mma_gemm<2><<<grid, 256, SMEM_MMA>>>(
            (const bf16*)p_yth, (const bf16*)p_ytl, (long)TT * CH,
            (const bf16*)p_pth, (const bf16*)p_ptl, (long)OO * CH,
            p_y2h, p_y2l, (long)TT * OO,
            TT, OO, CH, gpwn, p_b);
    }

    // 5) GEMM3: out = y2 . w2^T + w2_b + x   M=TT, N=DIN, K=OO
    {
        dim3 grid(DIN / MBN, TT / MBM, BB);
        mma_gemm<3><<<grid, 256, SMEM_MMA>>>(
            (const bf16*)p_y2h, (const bf16*)p_y2l, (long)TT * OO,
            (const bf16*)p_w2h, (const bf16*)p_w2l, 0L,
            out, nullptr, (long)TT * DIN,
            TT, DIN, OO, w2_b, x);
    }
}

// round 4
// speedup vs baseline: 2.2107x; 1.1348x over previous
#include <cuda_runtime.h>
#include <cuda_bf16.h>
#include <math.h>
#include <stdint.h>

// Problem constants
#define BB   8
#define TT   1024
#define DIN  256
#define CH   1024   // D_H1
#define OO   1024   // D_H2
#define KW   9

typedef __nv_bfloat16 bf16;

// Scratch (device globals — no allocation allowed)
__device__ float g_h [BB * CH * TT];     // mish(w1(x)), [b][c][t]
__device__ float g_pwn[BB * OO];         // 1/||p_w[b,:,o]||
__device__ float g_dwn[BB * KW];         // 1/||d_w[b,:,k]||
// bf16 hi/lo operands
__device__ bf16 g_yTh[BB * TT * CH];     // conv output, [b][t][c]
__device__ bf16 g_yTl[BB * TT * CH];
__device__ bf16 g_pTh[BB * OO * CH];     // [b][o][c]
__device__ bf16 g_pTl[BB * OO * CH];
__device__ bf16 g_y2h[BB * TT * OO];     // [b][t][o]
__device__ bf16 g_y2l[BB * TT * OO];
__device__ bf16 g_xh [BB * TT * DIN];    // [b][t][i]
__device__ bf16 g_xl [BB * TT * DIN];
__device__ bf16 g_w1h[CH * DIN];
__device__ bf16 g_w1l[CH * DIN];
__device__ bf16 g_w2h[DIN * OO];
__device__ bf16 g_w2l[DIN * OO];

__device__ __forceinline__ float mishf(float v) {
    float sp = (v > 20.f) ? v : log1pf(__expf(v));
    return v * tanhf(sp);
}

// ---------------------------------------------------------------------------
// Norm kernels
// ---------------------------------------------------------------------------
__global__ void dwn_kernel(const float* __restrict__ d_w) {
    int b = blockIdx.x / KW, k = blockIdx.x % KW;
    __shared__ float red[256];
    float s = 0.f;
    for (int c = threadIdx.x; c < CH; c += 256) {
        float v = d_w[((long)b * CH + c) * KW + k];
        s += v * v;
    }
    red[threadIdx.x] = s;
    __syncthreads();
    for (int off = 128; off > 0; off >>= 1) {
        if (threadIdx.x < off) red[threadIdx.x] += red[threadIdx.x + off];
        __syncthreads();
    }
    if (threadIdx.x == 0)
        g_dwn[b * KW + k] = 1.f / fmaxf(sqrtf(red[0]), 1e-12f);
}

__global__ void pwn_kernel(const float* __restrict__ p_w) {
    int b  = blockIdx.x / (OO / 32);
    int o0 = (blockIdx.x % (OO / 32)) * 32;
    int oi = threadIdx.x & 31, cg = threadIdx.x >> 5;
    int o = o0 + oi;
    float s = 0.f;
    for (int c = cg; c < CH; c += 8) {
        float v = p_w[((long)b * CH + c) * OO + o];
        s += v * v;
    }
    __shared__ float red[8][33];
    red[cg][oi] = s;
    __syncthreads();
    if (cg == 0) {
        float t = 0.f;
        #pragma unroll
        for (int j = 0; j < 8; j++) t += red[j][oi];
        g_pwn[b * OO + o] = 1.f / fmaxf(sqrtf(t), 1e-12f);
    }
}

// ---------------------------------------------------------------------------
// Fused: depthwise conv (K=9, pad 4) + transpose + bf16 hi/lo split
//   reads g_h[b][c][t], writes yT hi/lo [b][t][c]
// Grid (TT/32, CH/32, BB), block (32, 8). smem tile padded to 41 (conflict-free
// column reads: 41 mod 32 = 9, gcd(9,32)=1).
// ---------------------------------------------------------------------------
__global__ void __launch_bounds__(256)
convT_kernel(const float* __restrict__ d_w, const float* __restrict__ d_g,
             const float* __restrict__ d_b, const float* __restrict__ p_g,
             bf16* __restrict__ hi, bf16* __restrict__ lo) {
    __shared__ float tile[32][41];
    int b = blockIdx.z, c0 = blockIdx.y * 32, t0 = blockIdx.x * 32;
    int tid = threadIdx.y * 32 + threadIdx.x;

    const float* hbase = g_h + ((size_t)b * CH + c0) * TT;
    #pragma unroll
    for (int i = tid; i < 32 * 40; i += 256) {
        int c = i / 40, j = i % 40;
        int t = t0 - 4 + j;
        tile[c][j] = (t >= 0 && t < TT) ? hbase[(size_t)c * TT + t] : 0.f;
    }
    __syncthreads();

    int tx = threadIdx.x;            // c_local; coalesced output writes over tx
    int c  = c0 + tx;
    float gg   = d_g[b * CH + c];
    float pg   = p_g[b * CH + c];
    float bias = d_b[b * CH + c];
    float w[KW];
    #pragma unroll
    for (int k = 0; k < KW; k++)
        w[k] = d_w[((size_t)b * CH + c) * KW + k] * g_dwn[b * KW + k] * gg;

    #pragma unroll
    for (int i = 0; i < 4; i++) {
        int tl = threadIdx.y + i * 8;
        float acc = bias;
        #pragma unroll
        for (int k = 0; k < KW; k++) acc = fmaf(tile[tx][tl + k], w[k], acc);
        float v = acc * pg;
        bf16 h = __float2bfloat16(v);
        bf16 l = __float2bfloat16(v - __bfloat162float(h));
        size_t o = ((size_t)(b * TT + t0 + tl)) * CH + c;
        hi[o] = h;
        lo[o] = l;
    }
}

// ---------------------------------------------------------------------------
// Elementwise bf16 hi/lo split (no transpose), float4-vectorized
// ---------------------------------------------------------------------------
__global__ void split_kernel(const float* __restrict__ src,
                             bf16* __restrict__ hi, bf16* __restrict__ lo,
                             int n4) {
    int i = blockIdx.x * blockDim.x + threadIdx.x;
    if (i >= n4) return;
    float4 v = ((const float4*)src)[i];
    bf16 h0 = __float2bfloat16(v.x), h1 = __float2bfloat16(v.y);
    bf16 h2 = __float2bfloat16(v.z), h3 = __float2bfloat16(v.w);
    __nv_bfloat162 hA; hA.x = h0; hA.y = h1;
    __nv_bfloat162 hB; hB.x = h2; hB.y = h3;
    __nv_bfloat162 lA, lB;
    lA.x = __float2bfloat16(v.x - __bfloat162float(h0));
    lA.y = __float2bfloat16(v.y - __bfloat162float(h1));
    lB.x = __float2bfloat16(v.z - __bfloat162float(h2));
    lB.y = __float2bfloat16(v.w - __bfloat162float(h3));
    ((__nv_bfloat162*)hi)[i * 2 + 0] = hA;
    ((__nv_bfloat162*)hi)[i * 2 + 1] = hB;
    ((__nv_bfloat162*)lo)[i * 2 + 0] = lA;
    ((__nv_bfloat162*)lo)[i * 2 + 1] = lB;
}

// ---------------------------------------------------------------------------
// Transpose + bf16 hi/lo split: src[b][R][C] fp32 -> hi/lo[b][C][R] bf16
// ---------------------------------------------------------------------------
__global__ void tcvt_kernel(const float* __restrict__ src,
                            bf16* __restrict__ hi, bf16* __restrict__ lo) {
    __shared__ float tile[32][33];
    int b  = blockIdx.z;
    int c0 = blockIdx.x * 32;
    int r0 = blockIdx.y * 32;
    int tx = threadIdx.x, ty = threadIdx.y;
    const float* s = src + ((size_t)b * 1024 + r0) * 1024 + c0;
    #pragma unroll
    for (int i = 0; i < 32; i += 8)
        tile[ty + i][tx] = s[(size_t)(ty + i) * 1024 + tx];
    __syncthreads();
    size_t ob = ((size_t)b * 1024 + c0) * 1024 + r0;
    #pragma unroll
    for (int i = 0; i < 32; i += 8) {
        float v = tile[tx][ty + i];
        bf16 h = __float2bfloat16(v);
        bf16 l = __float2bfloat16(v - __bfloat162float(h));
        hi[ob + (size_t)(ty + i) * 1024 + tx] = h;
        lo[ob + (size_t)(ty + i) * 1024 + tx] = l;
    }
}

// ---------------------------------------------------------------------------
// Warp-MMA helpers (baseline ISA: sm_80+, works on .target sm_100)
// ---------------------------------------------------------------------------
__device__ __forceinline__ uint32_t smem_u32(const void* p) {
    uint32_t a;
    asm("{ .reg .u64 t; cvta.to.shared.u64 t, %1; cvt.u32.u64 %0, t; }"
        : "=r"(a) : "l"(p));
    return a;
}

__device__ __forceinline__ void cpa16(uint32_t s, const void* g) {
    asm volatile("cp.async.cg.shared.global [%0], [%1], 16;"
                 :: "r"(s), "l"(g) : "memory");
}

__device__ __forceinline__ void ldsm4(uint32_t* r, uint32_t a) {
    asm volatile("ldmatrix.sync.aligned.m8n8.x4.shared.b16 {%0,%1,%2,%3}, [%4];"
                 : "=r"(r[0]), "=r"(r[1]), "=r"(r[2]), "=r"(r[3]) : "r"(a));
}

__device__ __forceinline__ void ldsm2(uint32_t* r, uint32_t a) {
    asm volatile("ldmatrix.sync.aligned.m8n8.x2.shared.b16 {%0,%1}, [%2];"
                 : "=r"(r[0]), "=r"(r[1]) : "r"(a));
}

__device__ __forceinline__ void mma16816(float* d, const uint32_t* a,
                                         const uint32_t* b) {
    asm volatile(
        "mma.sync.aligned.m16n8k16.row.col.f32.bf16.bf16.f32 "
        "{%0,%1,%2,%3}, {%4,%5,%6,%7}, {%8,%9}, {%0,%1,%2,%3};"
        : "+f"(d[0]), "+f"(d[1]), "+f"(d[2]), "+f"(d[3])
        : "r"(a[0]), "r"(a[1]), "r"(a[2]), "r"(a[3]), "r"(b[0]), "r"(b[1]));
}

// ---------------------------------------------------------------------------
// bf16 hi/lo split GEMM: C[m][n] = sum_k A(m,k)*B(n,k), 3-pass
// A: [M][K] k-major (hi/lo), B: [N][K] k-major (hi/lo).
// CTA 128x128, BK=32, 8 warps (2x4), warp tile 64x32, cp.async double buffer.
// 2 CTAs/SM (smem 80KB x2 = 160KB <= 227KB carve-out; regs capped at 128).
// EPI 1: fp32 out = mish(v + e1[m])            (GEMM1)
// EPI 2: bf16 hi/lo out = v*e1[b*OO+n]+e2[..]  (GEMM2, split output)
// EPI 3: fp32 out = v + e1[n] + e2[b][m][n]    (GEMM3, residual)
// ---------------------------------------------------------------------------
#define MBM 128
#define MBN 128
#define MBK 32
#define ASTR 40                       // bf16 per smem row (80 B, conflict-free)
#define SEG  (128 * ASTR * 2)         // 10240 B per operand segment
#define STG  (4 * SEG)                // Ah,Al,Bh,Bl per stage
#define SMEM_MMA (2 * STG)            // 81920 B

template<int EPI>
__global__ void __launch_bounds__(256, 2)
mma_gemm(const bf16* __restrict__ Ah, const bf16* __restrict__ Al, long sA,
         const bf16* __restrict__ Bh, const bf16* __restrict__ Bl, long sB,
         void* __restrict__ C0, void* __restrict__ C1, long sC,
         int M, int N, int K,
         const float* __restrict__ e1, const float* __restrict__ e2)
{
    extern __shared__ __align__(128) char sm[];
    const uint32_t smb = smem_u32(sm);
    const int tid = threadIdx.x, lane = tid & 31, wid = tid >> 5;
    const int b = blockIdx.z;
    const int m0 = blockIdx.y * MBM, n0 = blockIdx.x * MBN;
    const int wm = wid >> 2, wn = wid & 3;

    const bf16* gAh = Ah + (size_t)b * sA + (size_t)m0 * K;
    const bf16* gAl = Al + (size_t)b * sA + (size_t)m0 * K;
    const bf16* gBh = Bh + (size_t)b * sB + (size_t)n0 * K;
    const bf16* gBl = Bl + (size_t)b * sB + (size_t)n0 * K;

    float acc[4][4][4];
    #pragma unroll
    for (int i = 0; i < 4; i++)
        #pragma unroll
        for (int j = 0; j < 4; j++)
            #pragma unroll
            for (int r = 0; r < 4; r++) acc[i][j][r] = 0.f;

    auto issue = [&](int kc, int s) {
        const uint32_t sb = smb + s * STG;
        #pragma unroll
        for (int t = 0; t < 2; t++) {
            int idx = tid + t * 256;          // 0..511
            int row = idx >> 2, c = idx & 3;
            uint32_t so = (uint32_t)(row * (ASTR * 2) + c * 16);
            size_t go = (size_t)row * K + (size_t)kc * MBK + c * 8;
            cpa16(sb + 0 * SEG + so, gAh + go);
            cpa16(sb + 1 * SEG + so, gAl + go);
            cpa16(sb + 2 * SEG + so, gBh + go);
            cpa16(sb + 3 * SEG + so, gBl + go);
        }
        asm volatile("cp.async.commit_group;" ::: "memory");
    };

    auto compute = [&](int s) {
        const uint32_t sb = smb + s * STG;
        #pragma unroll
        for (int ks = 0; ks < 2; ks++) {
            uint32_t ah[4][4], al[4][4], bh[4][2], bl[4][2];
            #pragma unroll
            for (int i = 0; i < 4; i++) {
                uint32_t ad = sb +
                    (uint32_t)((wm * 64 + i * 16 + (lane & 15)) * (ASTR * 2)) +
                    ks * 32 + (lane >> 4) * 16;
                ldsm4(ah[i], ad);
                ldsm4(al[i], ad + SEG);
            }
            #pragma unroll
            for (int j = 0; j < 4; j++) {
                uint32_t bd = sb + 2 * SEG +
                    (uint32_t)((wn * 32 + j * 8 + (lane & 7)) * (ASTR * 2)) +
                    ks * 32 + ((lane >> 3) & 1) * 16;
                ldsm2(bh[j], bd);
                ldsm2(bl[j], bd + SEG);
            }
            #pragma unroll
            for (int i = 0; i < 4; i++)
                #pragma unroll
                for (int j = 0; j < 4; j++) {
                    mma16816(acc[i][j], ah[i], bh[j]);
                    mma16816(acc[i][j], ah[i], bl[j]);
                    mma16816(acc[i][j], al[i], bh[j]);
                }
        }
    };

    const int NK = K / MBK;
    issue(0, 0);
    for (int kc = 0; kc < NK; kc++) {
        asm volatile("cp.async.wait_group 0;" ::: "memory");
        __syncthreads();
        if (kc + 1 < NK) issue(kc + 1, (kc + 1) & 1);
        compute(kc & 1);
        __syncthreads();
    }

    // --- epilogue ---
    const float* E1 = e1;
    const float* E2 = e2;
    if (EPI == 2) { E1 = e1 + b * OO; E2 = e2 + b * OO; }
    if (EPI == 3) { E2 = e2 + (size_t)b * M * N; }

    const int mrow0 = m0 + wm * 64;
    const int ncol0 = n0 + wn * 32;
    #pragma unroll
    for (int i = 0; i < 4; i++) {
        #pragma unroll
        for (int r = 0; r < 2; r++) {
            int m = mrow0 + i * 16 + (lane >> 2) + r * 8;
            #pragma unroll
            for (int j = 0; j < 4; j++) {
                int n = ncol0 + j * 8 + (lane & 3) * 2;
                float v0 = acc[i][j][r * 2 + 0];
                float v1 = acc[i][j][r * 2 + 1];
                size_t off = (size_t)m * N + n;
                if (EPI == 1) {
                    float bb = E1[m];
                    float2 o; o.x = mishf(v0 + bb); o.y = mishf(v1 + bb);
                    *(float2*)((float*)C0 + (size_t)b * sC + off) = o;
                } else if (EPI == 2) {
                    v0 = v0 * E1[n] + E2[n];
                    v1 = v1 * E1[n + 1] + E2[n + 1];
                    __nv_bfloat162 hv, lv;
                    hv.x = __float2bfloat16(v0);
                    hv.y = __float2bfloat16(v1);
                    lv.x = __float2bfloat16(v0 - __bfloat162float(hv.x));
                    lv.y = __float2bfloat16(v1 - __bfloat162float(hv.y));
                    *(__nv_bfloat162*)((bf16*)C0 + (size_t)b * sC + off) = hv;
                    *(__nv_bfloat162*)((bf16*)C1 + (size_t)b * sC + off) = lv;
                } else {
                    float2 o;
                    o.x = v0 + E1[n]     + E2[off];
                    o.y = v1 + E1[n + 1] + E2[off + 1];
                    *(float2*)((float*)C0 + (size_t)b * sC + off) = o;
                }
            }
        }
    }
}

// ---------------------------------------------------------------------------
extern "C" void kernel_launch(void* const* d_in, const int* in_sizes, int n_in,
                              void* d_out, int out_size) {
    const float* x    = (const float*)d_in[0];
    const float* d_w  = (const float*)d_in[1];
    const float* d_g  = (const float*)d_in[2];
    const float* d_b  = (const float*)d_in[3];
    const float* p_w  = (const float*)d_in[4];
    const float* p_g  = (const float*)d_in[5];
    const float* p_b  = (const float*)d_in[6];
    const float* w1_w = (const float*)d_in[7];
    const float* w1_b = (const float*)d_in[8];
    const float* w2_w = (const float*)d_in[9];
    const float* w2_b = (const float*)d_in[10];
    float* out = (float*)d_out;

    void *p_gh, *p_gpwn;
    void *p_yth, *p_ytl, *p_pth, *p_ptl, *p_y2h, *p_y2l;
    void *p_xh, *p_xl, *p_w1h, *p_w1l, *p_w2h, *p_w2l;
    cudaGetSymbolAddress(&p_gh,   g_h);
    cudaGetSymbolAddress(&p_gpwn, g_pwn);
    cudaGetSymbolAddress(&p_yth,  g_yTh);
    cudaGetSymbolAddress(&p_ytl,  g_yTl);
    cudaGetSymbolAddress(&p_pth,  g_pTh);
    cudaGetSymbolAddress(&p_ptl,  g_pTl);
    cudaGetSymbolAddress(&p_y2h,  g_y2h);
    cudaGetSymbolAddress(&p_y2l,  g_y2l);
    cudaGetSymbolAddress(&p_xh,   g_xh);
    cudaGetSymbolAddress(&p_xl,   g_xl);
    cudaGetSymbolAddress(&p_w1h,  g_w1h);
    cudaGetSymbolAddress(&p_w1l,  g_w1l);
    cudaGetSymbolAddress(&p_w2h,  g_w2h);
    cudaGetSymbolAddress(&p_w2l,  g_w2l);
    float* gh   = (float*)p_gh;
    float* gpwn = (float*)p_gpwn;

    cudaFuncSetAttribute(mma_gemm<1>,
                         cudaFuncAttributeMaxDynamicSharedMemorySize, SMEM_MMA);
    cudaFuncSetAttribute(mma_gemm<2>,
                         cudaFuncAttributeMaxDynamicSharedMemorySize, SMEM_MMA);
    cudaFuncSetAttribute(mma_gemm<3>,
                         cudaFuncAttributeMaxDynamicSharedMemorySize, SMEM_MMA);

    // 1) norms + input conversions
    dwn_kernel<<<BB * KW, 256>>>(d_w);
    pwn_kernel<<<BB * (OO / 32), 256>>>(p_w);
    split_kernel<<<(BB * TT * DIN / 4 + 255) / 256, 256>>>(
        x, (bf16*)p_xh, (bf16*)p_xl, BB * TT * DIN / 4);
    split_kernel<<<(CH * DIN / 4 + 255) / 256, 256>>>(
        w1_w, (bf16*)p_w1h, (bf16*)p_w1l, CH * DIN / 4);
    split_kernel<<<(DIN * OO / 4 + 255) / 256, 256>>>(
        w2_w, (bf16*)p_w2h, (bf16*)p_w2l, DIN * OO / 4);
    {
        dim3 grid(32, 32, BB);
        tcvt_kernel<<<grid, dim3(32, 8)>>>(p_w, (bf16*)p_pth, (bf16*)p_ptl);
    }

    // 2) GEMM1: h[b][c][t] = mish(w1 . x + w1_b)   M=CH, N=TT, K=DIN
    {
        dim3 grid(TT / MBN, CH / MBM, BB);
        mma_gemm<1><<<grid, 256, SMEM_MMA>>>(
            (const bf16*)p_w1h, (const bf16*)p_w1l, 0L,
            (const bf16*)p_xh,  (const bf16*)p_xl,  (long)TT * DIN,
            gh, nullptr, (long)CH * TT,
            CH, TT, DIN, w1_b, nullptr);
    }

    // 3) fused conv + transpose + split -> yT hi/lo
    {
        dim3 grid(TT / 32, CH / 32, BB);
        convT_kernel<<<grid, dim3(32, 8)>>>(d_w, d_g, d_b, p_g,
                                            (bf16*)p_yth, (bf16*)p_ytl);
    }

    // 4) GEMM2: y2[b][t][o] = (yT . pT)*pwn + p_b   M=TT, N=OO, K=CH
    {
        dim3 grid(OO / MBN, TT / MBM, BB);
        mma_gemm<2><<<grid, 256, SMEM_MMA>>>(
            (const bf16*)p_yth, (const bf16*)p_ytl, (long)TT * CH,
            (const bf16*)p_pth, (const bf16*)p_ptl, (long)OO * CH,
            p_y2h, p_y2l, (long)TT * OO,
            TT, OO, CH, gpwn, p_b);
    }

    // 5) GEMM3: out = y2 . w2^T + w2_b + x   M=TT, N=DIN, K=OO
    {
        dim3 grid(DIN / MBN, TT / MBM, BB);
        mma_gemm<3><<<grid, 256, SMEM_MMA>>>(
            (const bf16*)p_y2h, (const bf16*)p_y2l, (long)TT * OO,
            (const bf16*)p_w2h, (const bf16*)p_w2l, 0L,
            out, nullptr, (long)TT * DIN,
            TT, DIN, OO, w2_b, x);
    }
}

// round 5
// speedup vs baseline: 2.6233x; 1.1867x over previous
#include <cuda_runtime.h>
#include <cuda_bf16.h>
#include <math.h>
#include <stdint.h>

// Problem constants
#define BB   8
#define TT   1024
#define DIN  256
#define CH   1024   // D_H1
#define OO   1024   // D_H2
#define KW   9

typedef __nv_bfloat16 bf16;

// Packed-panel format for GEMM operands:
//   operand [R][K] (K-major)  ->  tiles of 128 rows x 32 k,
//   byte offset = ((r>>7)*nks + (k>>5))*SEGB + (r&127)*PROWB + (k&31)*2
//   PROWB=80 bakes the conflict-free padded smem row into global memory,
//   so one cp.async.bulk per 128x32 segment lands ready for ldmatrix.
#define PROWB 80
#define SEGB  10240                     // 128 * 80
#define PB_X   (8 * 8 * SEGB)           // per-batch packed x   [1024][256]
#define PB_1K  (8 * 32 * SEGB)          // per-batch packed [1024][1024]
#define PB_W2  (2 * 32 * SEGB)          // packed w2 [256][1024]

__device__ __forceinline__ size_t pk_off(int r, int k, int nks) {
    return (size_t)((r >> 7) * nks + (k >> 5)) * SEGB +
           (size_t)(r & 127) * PROWB + (size_t)(k & 31) * 2;
}

// Scratch (device globals — no allocation allowed)
__device__ float g_h [BB * CH * TT];     // mish(w1(x)), [b][c][t]
__device__ float g_pwn[BB * OO];
__device__ float g_dwn[BB * KW];
__device__ __align__(128) char g_xph [BB * PB_X];
__device__ __align__(128) char g_xpl [BB * PB_X];
__device__ __align__(128) char g_w1ph[8 * 8 * SEGB];
__device__ __align__(128) char g_w1pl[8 * 8 * SEGB];
__device__ __align__(128) char g_w2ph[PB_W2];
__device__ __align__(128) char g_w2pl[PB_W2];
__device__ __align__(128) char g_pTph[BB * PB_1K];
__device__ __align__(128) char g_pTpl[BB * PB_1K];
__device__ __align__(128) char g_yTph[BB * PB_1K];
__device__ __align__(128) char g_yTpl[BB * PB_1K];
__device__ __align__(128) char g_y2ph[BB * PB_1K];
__device__ __align__(128) char g_y2pl[BB * PB_1K];

__device__ __forceinline__ float mishf(float v) {
    float sp = (v > 20.f) ? v : log1pf(__expf(v));
    return v * tanhf(sp);
}

// ---------------------------------------------------------------------------
// Norm kernels
// ---------------------------------------------------------------------------
__global__ void dwn_kernel(const float* __restrict__ d_w) {
    int b = blockIdx.x / KW, k = blockIdx.x % KW;
    __shared__ float red[256];
    float s = 0.f;
    for (int c = threadIdx.x; c < CH; c += 256) {
        float v = d_w[((long)b * CH + c) * KW + k];
        s += v * v;
    }
    red[threadIdx.x] = s;
    __syncthreads();
    for (int off = 128; off > 0; off >>= 1) {
        if (threadIdx.x < off) red[threadIdx.x] += red[threadIdx.x + off];
        __syncthreads();
    }
    if (threadIdx.x == 0)
        g_dwn[b * KW + k] = 1.f / fmaxf(sqrtf(red[0]), 1e-12f);
}

__global__ void pwn_kernel(const float* __restrict__ p_w) {
    int b  = blockIdx.x / (OO / 32);
    int o0 = (blockIdx.x % (OO / 32)) * 32;
    int oi = threadIdx.x & 31, cg = threadIdx.x >> 5;
    int o = o0 + oi;
    float s = 0.f;
    for (int c = cg; c < CH; c += 8) {
        float v = p_w[((long)b * CH + c) * OO + o];
        s += v * v;
    }
    __shared__ float red[8][33];
    red[cg][oi] = s;
    __syncthreads();
    if (cg == 0) {
        float t = 0.f;
        #pragma unroll
        for (int j = 0; j < 8; j++) t += red[j][oi];
        g_pwn[b * OO + o] = 1.f / fmaxf(sqrtf(t), 1e-12f);
    }
}

// ---------------------------------------------------------------------------
// Fused: depthwise conv + transpose + hi/lo split, packed output
// reads g_h[b][c][t], writes yT packed (rows=t, k=c)
// ---------------------------------------------------------------------------
__global__ void __launch_bounds__(256)
convT_kernel(const float* __restrict__ d_w, const float* __restrict__ d_g,
             const float* __restrict__ d_b, const float* __restrict__ p_g,
             char* __restrict__ hi, char* __restrict__ lo) {
    __shared__ float tile[32][41];
    int b = blockIdx.z, c0 = blockIdx.y * 32, t0 = blockIdx.x * 32;
    int tid = threadIdx.y * 32 + threadIdx.x;

    const float* hbase = g_h + ((size_t)b * CH + c0) * TT;
    #pragma unroll
    for (int i = tid; i < 32 * 40; i += 256) {
        int c = i / 40, j = i % 40;
        int t = t0 - 4 + j;
        tile[c][j] = (t >= 0 && t < TT) ? hbase[(size_t)c * TT + t] : 0.f;
    }
    __syncthreads();

    int tx = threadIdx.x;
    int c  = c0 + tx;
    float gg   = d_g[b * CH + c];
    float pg   = p_g[b * CH + c];
    float bias = d_b[b * CH + c];
    float w[KW];
    #pragma unroll
    for (int k = 0; k < KW; k++)
        w[k] = d_w[((size_t)b * CH + c) * KW + k] * g_dwn[b * KW + k] * gg;

    #pragma unroll
    for (int i = 0; i < 4; i++) {
        int tl = threadIdx.y + i * 8;
        float acc = bias;
        #pragma unroll
        for (int k = 0; k < KW; k++) acc = fmaf(tile[tx][tl + k], w[k], acc);
        float v = acc * pg;
        bf16 h = __float2bfloat16(v);
        bf16 l = __float2bfloat16(v - __bfloat162float(h));
        size_t off = (size_t)b * PB_1K + pk_off(t0 + tl, c, 32);
        *(bf16*)(hi + off) = h;
        *(bf16*)(lo + off) = l;
    }
}

// ---------------------------------------------------------------------------
// Elementwise hi/lo split to packed format. src: [batches][R][K] fp32.
// ---------------------------------------------------------------------------
__global__ void splitp_kernel(const float* __restrict__ src,
                              char* __restrict__ hi, char* __restrict__ lo,
                              int R, int K, long pb_bytes, int n4total) {
    int i = blockIdx.x * blockDim.x + threadIdx.x;
    if (i >= n4total) return;
    long e = (long)i * 4;
    long perb = (long)R * K;
    int bb = (int)(e / perb);
    long rem = e - (long)bb * perb;
    int r = (int)(rem / K), k = (int)(rem % K);
    float4 v = ((const float4*)src)[i];
    bf16 h0 = __float2bfloat16(v.x), h1 = __float2bfloat16(v.y);
    bf16 h2 = __float2bfloat16(v.z), h3 = __float2bfloat16(v.w);
    __nv_bfloat162 hA, hB, lA, lB;
    hA.x = h0; hA.y = h1; hB.x = h2; hB.y = h3;
    lA.x = __float2bfloat16(v.x - __bfloat162float(h0));
    lA.y = __float2bfloat16(v.y - __bfloat162float(h1));
    lB.x = __float2bfloat16(v.z - __bfloat162float(h2));
    lB.y = __float2bfloat16(v.w - __bfloat162float(h3));
    size_t off = (size_t)bb * pb_bytes + pk_off(r, k, K >> 5);
    uint2 hw, lw;
    hw.x = *(uint32_t*)&hA; hw.y = *(uint32_t*)&hB;
    lw.x = *(uint32_t*)&lA; lw.y = *(uint32_t*)&lB;
    *(uint2*)(hi + off) = hw;
    *(uint2*)(lo + off) = lw;
}

// ---------------------------------------------------------------------------
// Transpose + split to packed: src[b][1024][1024] -> packed rows = src cols
// ---------------------------------------------------------------------------
__global__ void tcvtp_kernel(const float* __restrict__ src,
                             char* __restrict__ hi, char* __restrict__ lo) {
    __shared__ float tile[32][33];
    int b  = blockIdx.z;
    int c0 = blockIdx.x * 32;
    int r0 = blockIdx.y * 32;
    int tx = threadIdx.x, ty = threadIdx.y;
    const float* s = src + ((size_t)b * 1024 + r0) * 1024 + c0;
    #pragma unroll
    for (int i = 0; i < 32; i += 8)
        tile[ty + i][tx] = s[(size_t)(ty + i) * 1024 + tx];
    __syncthreads();
    #pragma unroll
    for (int i = 0; i < 32; i += 8) {
        float v = tile[tx][ty + i];
        bf16 h = __float2bfloat16(v);
        bf16 l = __float2bfloat16(v - __bfloat162float(h));
        size_t off = (size_t)b * PB_1K + pk_off(c0 + ty + i, r0 + tx, 32);
        *(bf16*)(hi + off) = h;
        *(bf16*)(lo + off) = l;
    }
}

// ---------------------------------------------------------------------------
// PTX helpers
// ---------------------------------------------------------------------------
__device__ __forceinline__ uint32_t smem_u32(const void* p) {
    uint32_t a;
    asm("{ .reg .u64 t; cvta.to.shared.u64 t, %1; cvt.u32.u64 %0, t; }"
        : "=r"(a) : "l"(p));
    return a;
}

__device__ __forceinline__ void mbar_init(uint32_t m, uint32_t cnt) {
    asm volatile("mbarrier.init.shared.b64 [%0], %1;" :: "r"(m), "r"(cnt)
                 : "memory");
}

__device__ __forceinline__ void mbar_expect(uint32_t m, uint32_t tx) {
    asm volatile("mbarrier.arrive.expect_tx.shared.b64 _, [%0], %1;"
                 :: "r"(m), "r"(tx) : "memory");
}

__device__ __forceinline__ void bulk_g2s(uint32_t dst, const void* src,
                                         uint32_t bytes, uint32_t mbar) {
    asm volatile(
        "cp.async.bulk.shared::cluster.global.mbarrier::complete_tx::bytes "
        "[%0], [%1], %2, [%3];"
        :: "r"(dst), "l"(src), "r"(bytes), "r"(mbar) : "memory");
}

__device__ __forceinline__ void mbar_wait(uint32_t m, uint32_t parity) {
    uint32_t done = 0;
    while (!done)
        asm volatile(
            "{ .reg .pred P; mbarrier.try_wait.parity.shared.b64 P, [%1], %2; "
            "selp.b32 %0,1,0,P; }"
            : "=r"(done) : "r"(m), "r"(parity) : "memory");
}

__device__ __forceinline__ void ldsm4(uint32_t* r, uint32_t a) {
    asm volatile("ldmatrix.sync.aligned.m8n8.x4.shared.b16 {%0,%1,%2,%3}, [%4];"
                 : "=r"(r[0]), "=r"(r[1]), "=r"(r[2]), "=r"(r[3]) : "r"(a));
}

__device__ __forceinline__ void ldsm2(uint32_t* r, uint32_t a) {
    asm volatile("ldmatrix.sync.aligned.m8n8.x2.shared.b16 {%0,%1}, [%2];"
                 : "=r"(r[0]), "=r"(r[1]) : "r"(a));
}

__device__ __forceinline__ void mma16816(float* d, const uint32_t* a,
                                         const uint32_t* b) {
    asm volatile(
        "mma.sync.aligned.m16n8k16.row.col.f32.bf16.bf16.f32 "
        "{%0,%1,%2,%3}, {%4,%5,%6,%7}, {%8,%9}, {%0,%1,%2,%3};"
        : "+f"(d[0]), "+f"(d[1]), "+f"(d[2]), "+f"(d[3])
        : "r"(a[0]), "r"(a[1]), "r"(a[2]), "r"(a[3]), "r"(b[0]), "r"(b[1]));
}

// ---------------------------------------------------------------------------
// bf16 hi/lo split GEMM on packed-panel operands, bulk-copy loader.
// C[m][n] = sum_k A(m,k)*B(n,k); 3 MMA passes (hh + hl + lh).
// CTA 128x128, BK=32, 8 warps, warp tile 64x32, double buffer, 2 CTAs/SM.
// EPI 1: fp32 C = mish(v + e1[m])
// EPI 2: packed bf16 hi/lo C = v*e1[b*OO+n] + e2[b*OO+n]
// EPI 3: fp32 C = v + e1[n] + e2[b][m][n]
// ---------------------------------------------------------------------------
#define ASTR 40
#define SEG  SEGB                        // 10240 B per operand segment
#define STG  (4 * SEG)
#define SMEM_MMA (2 * STG + 16)          // + 2 mbarriers

template<int EPI>
__global__ void __launch_bounds__(256, 2)
mma_gemm(const char* __restrict__ Ah, const char* __restrict__ Al, long sA,
         const char* __restrict__ Bh, const char* __restrict__ Bl, long sB,
         void* __restrict__ C0, void* __restrict__ C1, long sC,
         int M, int N, int K,
         const float* __restrict__ e1, const float* __restrict__ e2)
{
    extern __shared__ __align__(128) char sm[];
    const uint32_t smb = smem_u32(sm);
    const uint32_t mb0 = smb + 2 * STG;
    const int tid = threadIdx.x, lane = tid & 31, wid = tid >> 5;
    const int b = blockIdx.z;
    const int m0 = blockIdx.y * 128, n0 = blockIdx.x * 128;
    const int wm = wid >> 2, wn = wid & 3;
    const int nk = K >> 5;

    const char* pAh = Ah + (size_t)b * sA + (size_t)(m0 >> 7) * nk * SEGB;
    const char* pAl = Al + (size_t)b * sA + (size_t)(m0 >> 7) * nk * SEGB;
    const char* pBh = Bh + (size_t)b * sB + (size_t)(n0 >> 7) * nk * SEGB;
    const char* pBl = Bl + (size_t)b * sB + (size_t)(n0 >> 7) * nk * SEGB;

    if (tid == 0) { mbar_init(mb0, 1); mbar_init(mb0 + 8, 1); }
    __syncthreads();

    float acc[4][4][4];
    #pragma unroll
    for (int i = 0; i < 4; i++)
        #pragma unroll
        for (int j = 0; j < 4; j++)
            #pragma unroll
            for (int r = 0; r < 4; r++) acc[i][j][r] = 0.f;

    auto issue = [&](int kc, int s) {
        if (tid == 0) {
            uint32_t mb = mb0 + s * 8;
            uint32_t sb = smb + s * STG;
            mbar_expect(mb, 4 * SEG);
            bulk_g2s(sb + 0 * SEG, pAh + (size_t)kc * SEGB, SEG, mb);
            bulk_g2s(sb + 1 * SEG, pAl + (size_t)kc * SEGB, SEG, mb);
            bulk_g2s(sb + 2 * SEG, pBh + (size_t)kc * SEGB, SEG, mb);
            bulk_g2s(sb + 3 * SEG, pBl + (size_t)kc * SEGB, SEG, mb);
        }
    };

    auto compute = [&](int s) {
        const uint32_t sb = smb + s * STG;
        #pragma unroll
        for (int ks = 0; ks < 2; ks++) {
            uint32_t ah[4][4], al[4][4], bh[4][2], bl[4][2];
            #pragma unroll
            for (int i = 0; i < 4; i++) {
                uint32_t ad = sb +
                    (uint32_t)((wm * 64 + i * 16 + (lane & 15)) * (ASTR * 2)) +
                    ks * 32 + (lane >> 4) * 16;
                ldsm4(ah[i], ad);
                ldsm4(al[i], ad + SEG);
            }
            #pragma unroll
            for (int j = 0; j < 4; j++) {
                uint32_t bd = sb + 2 * SEG +
                    (uint32_t)((wn * 32 + j * 8 + (lane & 7)) * (ASTR * 2)) +
                    ks * 32 + ((lane >> 3) & 1) * 16;
                ldsm2(bh[j], bd);
                ldsm2(bl[j], bd + SEG);
            }
            #pragma unroll
            for (int i = 0; i < 4; i++)
                #pragma unroll
                for (int j = 0; j < 4; j++) {
                    mma16816(acc[i][j], ah[i], bh[j]);
                    mma16816(acc[i][j], ah[i], bl[j]);
                    mma16816(acc[i][j], al[i], bh[j]);
                }
        }
    };

    issue(0, 0);
    if (nk > 1) issue(1, 1);
    for (int kc = 0; kc < nk; kc++) {
        int s = kc & 1;
        mbar_wait(mb0 + s * 8, (kc >> 1) & 1);
        compute(s);
        __syncthreads();
        if (kc + 2 < nk) issue(kc + 2, s);
    }

    // --- epilogue ---
    const float* E1 = e1;
    const float* E2 = e2;
    if (EPI == 2) { E1 = e1 + b * OO; E2 = e2 + b * OO; }
    if (EPI == 3) { E2 = e2 + (size_t)b * M * N; }

    char* C0b = (char*)C0 + (size_t)b * sC;
    char* C1b = (char*)C1 + (EPI == 2 ? (size_t)b * sC : 0);

    const int mrow0 = m0 + wm * 64;
    const int ncol0 = n0 + wn * 32;
    #pragma unroll
    for (int i = 0; i < 4; i++) {
        #pragma unroll
        for (int r = 0; r < 2; r++) {
            int m = mrow0 + i * 16 + (lane >> 2) + r * 8;
            #pragma unroll
            for (int j = 0; j < 4; j++) {
                int n = ncol0 + j * 8 + (lane & 3) * 2;
                float v0 = acc[i][j][r * 2 + 0];
                float v1 = acc[i][j][r * 2 + 1];
                size_t off = (size_t)m * N + n;
                if (EPI == 1) {
                    float bb = E1[m];
                    float2 o; o.x = mishf(v0 + bb); o.y = mishf(v1 + bb);
                    *(float2*)((float*)C0b + off) = o;
                } else if (EPI == 2) {
                    v0 = v0 * E1[n] + E2[n];
                    v1 = v1 * E1[n + 1] + E2[n + 1];
                    __nv_bfloat162 hv, lv;
                    hv.x = __float2bfloat16(v0);
                    hv.y = __float2bfloat16(v1);
                    lv.x = __float2bfloat16(v0 - __bfloat162float(hv.x));
                    lv.y = __float2bfloat16(v1 - __bfloat162float(hv.y));
                    size_t po = pk_off(m, n, N >> 5);
                    *(uint32_t*)(C0b + po) = *(uint32_t*)&hv;
                    *(uint32_t*)(C1b + po) = *(uint32_t*)&lv;
                } else {
                    float2 o;
                    o.x = v0 + E1[n]     + E2[off];
                    o.y = v1 + E1[n + 1] + E2[off + 1];
                    *(float2*)((float*)C0b + off) = o;
                }
            }
        }
    }
}

// ---------------------------------------------------------------------------
extern "C" void kernel_launch(void* const* d_in, const int* in_sizes, int n_in,
                              void* d_out, int out_size) {
    const float* x    = (const float*)d_in[0];
    const float* d_w  = (const float*)d_in[1];
    const float* d_g  = (const float*)d_in[2];
    const float* d_b  = (const float*)d_in[3];
    const float* p_w  = (const float*)d_in[4];
    const float* p_g  = (const float*)d_in[5];
    const float* p_b  = (const float*)d_in[6];
    const float* w1_w = (const float*)d_in[7];
    const float* w1_b = (const float*)d_in[8];
    const float* w2_w = (const float*)d_in[9];
    const float* w2_b = (const float*)d_in[10];
    float* out = (float*)d_out;

    void *p_gh, *p_gpwn;
    void *p_xh, *p_xl, *p_w1h, *p_w1l, *p_w2h, *p_w2l;
    void *p_pth, *p_ptl, *p_yth, *p_ytl, *p_y2h, *p_y2l;
    cudaGetSymbolAddress(&p_gh,   g_h);
    cudaGetSymbolAddress(&p_gpwn, g_pwn);
    cudaGetSymbolAddress(&p_xh,   g_xph);
    cudaGetSymbolAddress(&p_xl,   g_xpl);
    cudaGetSymbolAddress(&p_w1h,  g_w1ph);
    cudaGetSymbolAddress(&p_w1l,  g_w1pl);
    cudaGetSymbolAddress(&p_w2h,  g_w2ph);
    cudaGetSymbolAddress(&p_w2l,  g_w2pl);
    cudaGetSymbolAddress(&p_pth,  g_pTph);
    cudaGetSymbolAddress(&p_ptl,  g_pTpl);
    cudaGetSymbolAddress(&p_yth,  g_yTph);
    cudaGetSymbolAddress(&p_ytl,  g_yTpl);
    cudaGetSymbolAddress(&p_y2h,  g_y2ph);
    cudaGetSymbolAddress(&p_y2l,  g_y2pl);
    float* gh   = (float*)p_gh;
    float* gpwn = (float*)p_gpwn;

    cudaFuncSetAttribute(mma_gemm<1>,
                         cudaFuncAttributeMaxDynamicSharedMemorySize, SMEM_MMA);
    cudaFuncSetAttribute(mma_gemm<2>,
                         cudaFuncAttributeMaxDynamicSharedMemorySize, SMEM_MMA);
    cudaFuncSetAttribute(mma_gemm<3>,
                         cudaFuncAttributeMaxDynamicSharedMemorySize, SMEM_MMA);

    // 1) norms + packed input conversions
    dwn_kernel<<<BB * KW, 256>>>(d_w);
    pwn_kernel<<<BB * (OO / 32), 256>>>(p_w);
    splitp_kernel<<<(BB * TT * DIN / 4 + 255) / 256, 256>>>(
        x, (char*)p_xh, (char*)p_xl, TT, DIN, PB_X, BB * TT * DIN / 4);
    splitp_kernel<<<(CH * DIN / 4 + 255) / 256, 256>>>(
        w1_w, (char*)p_w1h, (char*)p_w1l, CH, DIN, 0L, CH * DIN / 4);
    splitp_kernel<<<(DIN * OO / 4 + 255) / 256, 256>>>(
        w2_w, (char*)p_w2h, (char*)p_w2l, DIN, OO, 0L, DIN * OO / 4);
    {
        dim3 grid(32, 32, BB);
        tcvtp_kernel<<<grid, dim3(32, 8)>>>(p_w, (char*)p_pth, (char*)p_ptl);
    }

    // 2) GEMM1: h = mish(w1 . x + w1_b)   M=CH, N=TT, K=DIN
    {
        dim3 grid(TT / 128, CH / 128, BB);
        mma_gemm<1><<<grid, 256, SMEM_MMA>>>(
            (char*)p_w1h, (char*)p_w1l, 0L,
            (char*)p_xh,  (char*)p_xl,  (long)PB_X,
            gh, nullptr, (long)CH * TT * 4,
            CH, TT, DIN, w1_b, nullptr);
    }

    // 3) fused conv + transpose + split -> yT packed
    {
        dim3 grid(TT / 32, CH / 32, BB);
        convT_kernel<<<grid, dim3(32, 8)>>>(d_w, d_g, d_b, p_g,
                                            (char*)p_yth, (char*)p_ytl);
    }

    // 4) GEMM2: y2 = (yT . pT)*pwn + p_b   M=TT, N=OO, K=CH  (packed out)
    {
        dim3 grid(OO / 128, TT / 128, BB);
        mma_gemm<2><<<grid, 256, SMEM_MMA>>>(
            (char*)p_yth, (char*)p_ytl, (long)PB_1K,
            (char*)p_pth, (char*)p_ptl, (long)PB_1K,
            p_y2h, p_y2l, (long)PB_1K,
            TT, OO, CH, gpwn, p_b);
    }

    // 5) GEMM3: out = y2 . w2^T + w2_b + x   M=TT, N=DIN, K=OO
    {
        dim3 grid(DIN / 128, TT / 128, BB);
        mma_gemm<3><<<grid, 256, SMEM_MMA>>>(
            (char*)p_y2h, (char*)p_y2l, (long)PB_1K,
            (char*)p_w2h, (char*)p_w2l, 0L,
            out, nullptr, (long)TT * DIN * 4,
            TT, DIN, OO, w2_b, x);
    }
}